// round 8
// baseline (speedup 1.0000x reference)
#include <cuda_runtime.h>

#define T_LEN  1024
#define BATCH  512
#define HID    64

__device__ float g_hbuf[T_LEN * HID];

// ---- packed f32x2 + MUFU helpers (sm_103a) ----
__device__ __forceinline__ unsigned long long fma2(unsigned long long a,
                                                   unsigned long long b,
                                                   unsigned long long c) {
    unsigned long long d;
    asm("fma.rn.f32x2 %0, %1, %2, %3;" : "=l"(d) : "l"(a), "l"(b), "l"(c));
    return d;
}
__device__ __forceinline__ unsigned long long add2(unsigned long long a,
                                                   unsigned long long b) {
    unsigned long long d;
    asm("add.rn.f32x2 %0, %1, %2;" : "=l"(d) : "l"(a), "l"(b));
    return d;
}
__device__ __forceinline__ unsigned long long pack2(float lo, float hi) {
    unsigned long long d;
    asm("mov.b64 %0, {%1, %2};" : "=l"(d) : "f"(lo), "f"(hi));
    return d;
}
__device__ __forceinline__ float tanh_fast(float x) {
    float r; asm("tanh.approx.f32 %0, %1;" : "=f"(r) : "f"(x)); return r;
}

// 128 threads / 4 warps. Warp w, lane l: role = l>>4, unit u = w*16 + (l&15).
//   role 0 owns rows i (u), g (128+u)   -> produces i*g, sends via shfl
//   role 1 owns rows f (64+u), o (192+u) -> sole owner of c, h
// Sigmoid rows pre-scaled by 0.5: sigmoid = fma(.5, tanh(gate), .5).
__global__ void __launch_bounds__(128, 1)
lstm_seq_kernel(const float* __restrict__ x,
                const float* __restrict__ W_ih,
                const float* __restrict__ W_hh,
                const float* __restrict__ b_ih,
                const float* __restrict__ b_hh,
                const float* __restrict__ W_fc,
                const float* __restrict__ b_fc,
                float* __restrict__ out)
{
    __shared__ float x_s[T_LEN * 2];
    __shared__ __align__(16) float h_s[2][HID];

    const int tid  = threadIdx.x;
    const int w    = tid >> 5;
    const int l    = tid & 31;
    const int role = l >> 4;
    const int u    = (w << 4) | (l & 15);
    const int rA   = role ? (HID + u) : u;                  // i | f  (sigmoid)
    const int rB   = role ? (3 * HID + u) : (2 * HID + u);  // g (tanh) | o (sigmoid)

    for (int i = tid; i < T_LEN * 2; i += 128) {
        const int t = i >> 1, c = i & 1;
        x_s[i] = x[(t * BATCH + (BATCH - 1)) * 2 + c];
    }

    const float sclA = 0.5f;                   // i, f sigmoids
    const float sclB = role ? 0.5f : 1.0f;     // o sigmoid, g tanh
    ulonglong2 wA[16], wB[16];
    {
        const float4* pA = reinterpret_cast<const float4*>(W_hh + rA * HID);
        const float4* pB = reinterpret_cast<const float4*>(W_hh + rB * HID);
#pragma unroll
        for (int i = 0; i < 16; ++i) {
            const float4 a = pA[i];
            const float4 b = pB[i];
            wA[i].x = pack2(a.x * sclA, a.y * sclA);
            wA[i].y = pack2(a.z * sclA, a.w * sclA);
            wB[i].x = pack2(b.x * sclB, b.y * sclB);
            wB[i].y = pack2(b.z * sclB, b.w * sclB);
        }
    }

    const float bjA  = (b_ih[rA] + b_hh[rA]) * sclA;
    const float bjB  = (b_ih[rB] + b_hh[rB]) * sclB;
    const float wiA0 = W_ih[rA * 2] * sclA, wiA1 = W_ih[rA * 2 + 1] * sclA;
    const float wiB0 = W_ih[rB * 2] * sclB, wiB1 = W_ih[rB * 2 + 1] * sclB;

    const float bB = role ? 0.5f : 1.0f;
    const float aB = role ? 0.5f : 0.0f;

    float c_state = 0.0f;                  // live only in role1
    if (tid < HID) h_s[0][tid] = 0.0f;
    __syncthreads();

#pragma unroll 1
    for (int t = 0; t < T_LEN; t += 4) {
#pragma unroll
        for (int ph = 0; ph < 4; ++ph) {
            const int tt = t + ph;
            const float2 xp = *reinterpret_cast<const float2*>(x_s + 2 * tt);
            const float gxA = fmaf(wiA0, xp.x, fmaf(wiA1, xp.y, bjA));
            const float gxB = fmaf(wiB0, xp.x, fmaf(wiB1, xp.y, bjB));

            const ulonglong2* hv =
                reinterpret_cast<const ulonglong2*>(h_s[ph & 1]);

            // 2+2 accumulator chains (A0,A1,B0,B1): reissue spacing 8 cyc > 4 lat
            unsigned long long aA0 = pack2(gxA, 0.0f), aA1 = 0ull;
            unsigned long long aB0 = pack2(gxB, 0.0f), aB1 = 0ull;
#pragma unroll
            for (int i = 0; i < 16; i += 2) {
                const ulonglong2 h0 = hv[i];
                const ulonglong2 h1 = hv[i + 1];
                aA0 = fma2(wA[i].x,     h0.x, aA0);
                aA1 = fma2(wA[i].y,     h0.y, aA1);
                aB0 = fma2(wB[i].x,     h0.x, aB0);
                aB1 = fma2(wB[i].y,     h0.y, aB1);
                aA0 = fma2(wA[i + 1].x, h1.x, aA0);
                aA1 = fma2(wA[i + 1].y, h1.y, aA1);
                aB0 = fma2(wB[i + 1].x, h1.x, aB0);
                aB1 = fma2(wB[i + 1].y, h1.y, aB1);
            }
            aA0 = add2(aA0, aA1);
            aB0 = add2(aB0, aB1);

            float loA, hiA, loB, hiB;
            asm("mov.b64 {%0, %1}, %2;" : "=f"(loA), "=f"(hiA) : "l"(aA0));
            asm("mov.b64 {%0, %1}, %2;" : "=f"(loB), "=f"(hiB) : "l"(aB0));

            const float gateA = loA + hiA;
            const float gateB = loB + hiB;

            const float actA = fmaf(0.5f, tanh_fast(gateA), 0.5f);  // i | f
            const float actB = fmaf(bB,   tanh_fast(gateB), aB);    // g | o

            // ONE shuffle: role0 sends i*g (role1's send value ignored)
            const float send = role ? 0.0f : actA * actB;
            const float recv = __shfl_xor_sync(0xffffffffu, send, 16);

            float h = 0.0f;
            if (role) {
                c_state = fmaf(actA, c_state, recv);   // f*c + i*g
                h = actB * tanh_fast(c_state);
                h_s[(ph & 1) ^ 1][u] = h;
            }
            __syncthreads();
            if (role) g_hbuf[tt * HID + u] = h;   // post-barrier, off chain
        }
    }

    // ---- Fused FC tail: out[t,o] = W_fc[o].h_t + b_fc[o]  (2048 outputs) ----
    {
        const int o     = tid & 1;
        const int tbase = (tid >> 1) * 16;
        ulonglong2 wf[16];
        {
            const float4* wrow = reinterpret_cast<const float4*>(W_fc + o * HID);
#pragma unroll
            for (int i = 0; i < 16; ++i) {
                const float4 v = wrow[i];
                wf[i].x = pack2(v.x, v.y);
                wf[i].y = pack2(v.z, v.w);
            }
        }
        const float bias = b_fc[o];
#pragma unroll 1
        for (int k = 0; k < 16; ++k) {
            const int tt = tbase + k;
            const ulonglong2* hv =
                reinterpret_cast<const ulonglong2*>(g_hbuf + tt * HID);
            unsigned long long a0 = 0ull, a1 = 0ull, a2 = 0ull, a3 = 0ull;
#pragma unroll
            for (int i = 0; i < 16; i += 2) {
                const ulonglong2 h0 = hv[i];
                const ulonglong2 h1 = hv[i + 1];
                a0 = fma2(wf[i].x,     h0.x, a0);
                a1 = fma2(wf[i].y,     h0.y, a1);
                a2 = fma2(wf[i + 1].x, h1.x, a2);
                a3 = fma2(wf[i + 1].y, h1.y, a3);
            }
            a0 = add2(a0, a1); a2 = add2(a2, a3); a0 = add2(a0, a2);
            float lo, hi;
            asm("mov.b64 {%0, %1}, %2;" : "=f"(lo), "=f"(hi) : "l"(a0));
            out[tt * 2 + o] = (lo + hi) + bias;
        }
    }
}

extern "C" void kernel_launch(void* const* d_in, const int* in_sizes, int n_in,
                              void* d_out, int out_size)
{
    const float* x    = (const float*)d_in[0];
    const float* W_ih = (const float*)d_in[1];
    const float* W_hh = (const float*)d_in[2];
    const float* b_ih = (const float*)d_in[3];
    const float* b_hh = (const float*)d_in[4];
    const float* W_fc = (const float*)d_in[5];
    const float* b_fc = (const float*)d_in[6];
    float* out = (float*)d_out;

    lstm_seq_kernel<<<1, 128>>>(x, W_ih, W_hh, b_ih, b_hh, W_fc, b_fc, out);
}

// round 10
// speedup vs baseline: 1.0250x; 1.0250x over previous
#include <cuda_runtime.h>

#define T_LEN  1024
#define BATCH  512
#define HID    64

__device__ float g_hbuf[T_LEN * HID];

// ---- packed f32x2 + MUFU helpers (sm_103a) ----
__device__ __forceinline__ unsigned long long fma2(unsigned long long a,
                                                   unsigned long long b,
                                                   unsigned long long c) {
    unsigned long long d;
    asm("fma.rn.f32x2 %0, %1, %2, %3;" : "=l"(d) : "l"(a), "l"(b), "l"(c));
    return d;
}
__device__ __forceinline__ unsigned long long add2(unsigned long long a,
                                                   unsigned long long b) {
    unsigned long long d;
    asm("add.rn.f32x2 %0, %1, %2;" : "=l"(d) : "l"(a), "l"(b));
    return d;
}
__device__ __forceinline__ unsigned long long pack2(float lo, float hi) {
    unsigned long long d;
    asm("mov.b64 %0, {%1, %2};" : "=l"(d) : "f"(lo), "f"(hi));
    return d;
}
__device__ __forceinline__ float tanh_fast(float x) {
    float r; asm("tanh.approx.f32 %0, %1;" : "=f"(r) : "f"(x)); return r;
}

// 128 threads / 4 warps. Warp w, lane l: role = l>>4, unit u = w*16 + (l&15).
//   role 0 owns rows i (u), g (128+u)   -> produces i*g, sends via shfl
//   role 1 owns rows f (64+u), o (192+u) -> sole owner of c, h
// Sigmoid rows pre-scaled by 0.5: sigmoid = fma(.5, tanh(gate), .5).
__global__ void __launch_bounds__(128, 1)
lstm_seq_kernel(const float* __restrict__ x,
                const float* __restrict__ W_ih,
                const float* __restrict__ W_hh,
                const float* __restrict__ b_ih,
                const float* __restrict__ b_hh,
                const float* __restrict__ W_fc,
                const float* __restrict__ b_fc,
                float* __restrict__ out)
{
    __shared__ float x_s[T_LEN * 2];
    __shared__ __align__(16) float h_s[2][HID];

    const int tid  = threadIdx.x;
    const int w    = tid >> 5;
    const int l    = tid & 31;
    const int role = l >> 4;
    const int u    = (w << 4) | (l & 15);
    const int rA   = role ? (HID + u) : u;                  // i | f  (sigmoid)
    const int rB   = role ? (3 * HID + u) : (2 * HID + u);  // g (tanh) | o (sigmoid)

    for (int i = tid; i < T_LEN * 2; i += 128) {
        const int t = i >> 1, c = i & 1;
        x_s[i] = x[(t * BATCH + (BATCH - 1)) * 2 + c];
    }

    const float sclA = 0.5f;                   // i, f sigmoids
    const float sclB = role ? 0.5f : 1.0f;     // o sigmoid, g tanh
    ulonglong2 wA[16], wB[16];
    {
        const float4* pA = reinterpret_cast<const float4*>(W_hh + rA * HID);
        const float4* pB = reinterpret_cast<const float4*>(W_hh + rB * HID);
#pragma unroll
        for (int i = 0; i < 16; ++i) {
            const float4 a = pA[i];
            const float4 b = pB[i];
            wA[i].x = pack2(a.x * sclA, a.y * sclA);
            wA[i].y = pack2(a.z * sclA, a.w * sclA);
            wB[i].x = pack2(b.x * sclB, b.y * sclB);
            wB[i].y = pack2(b.z * sclB, b.w * sclB);
        }
    }

    const float bjA  = (b_ih[rA] + b_hh[rA]) * sclA;
    const float bjB  = (b_ih[rB] + b_hh[rB]) * sclB;
    const float wiA0 = W_ih[rA * 2] * sclA, wiA1 = W_ih[rA * 2 + 1] * sclA;
    const float wiB0 = W_ih[rB * 2] * sclB, wiB1 = W_ih[rB * 2 + 1] * sclB;

    const float bB = role ? 0.5f : 1.0f;   // role1 (o): sigmoid post-scale
    const float aB = role ? 0.5f : 0.0f;

    float c_state = 0.0f;                  // live only in role1
    if (tid < HID) h_s[0][tid] = 0.0f;
    __syncthreads();

#pragma unroll 1
    for (int t = 0; t < T_LEN; t += 2) {
#pragma unroll
        for (int ph = 0; ph < 2; ++ph) {
            const int tt = t + ph;
            const float2 xp = *reinterpret_cast<const float2*>(x_s + 2 * tt);
            const float gxA = fmaf(wiA0, xp.x, fmaf(wiA1, xp.y, bjA));
            const float gxB = fmaf(wiB0, xp.x, fmaf(wiB1, xp.y, bjB));

            const ulonglong2* hv = reinterpret_cast<const ulonglong2*>(h_s[ph]);

            // 8 accumulator chains (R7 structure — best measured)
            unsigned long long aA0 = pack2(gxA, 0.0f), aA1 = 0ull, aA2 = 0ull, aA3 = 0ull;
            unsigned long long aB0 = pack2(gxB, 0.0f), aB1 = 0ull, aB2 = 0ull, aB3 = 0ull;
#pragma unroll
            for (int i = 0; i < 16; i += 2) {
                const ulonglong2 h0 = hv[i];
                const ulonglong2 h1 = hv[i + 1];
                aA0 = fma2(wA[i].x,     h0.x, aA0);
                aA1 = fma2(wA[i].y,     h0.y, aA1);
                aA2 = fma2(wA[i + 1].x, h1.x, aA2);
                aA3 = fma2(wA[i + 1].y, h1.y, aA3);
                aB0 = fma2(wB[i].x,     h0.x, aB0);
                aB1 = fma2(wB[i].y,     h0.y, aB1);
                aB2 = fma2(wB[i + 1].x, h1.x, aB2);
                aB3 = fma2(wB[i + 1].y, h1.y, aB3);
            }
            aA0 = add2(aA0, aA1); aA2 = add2(aA2, aA3); aA0 = add2(aA0, aA2);
            aB0 = add2(aB0, aB1); aB2 = add2(aB2, aB3); aB0 = add2(aB0, aB2);

            float loA, hiA, loB, hiB;
            asm("mov.b64 {%0, %1}, %2;" : "=f"(loA), "=f"(hiA) : "l"(aA0));
            asm("mov.b64 {%0, %1}, %2;" : "=f"(loB), "=f"(hiB) : "l"(aB0));

            const float gateA = loA + hiA;
            const float gateB = loB + hiB;

            const float actA = fmaf(0.5f, tanh_fast(gateA), 0.5f);  // i | f
            const float thB  = tanh_fast(gateB);                    // g | pre-o

            // role0: send = tanh(gB) * actA  (g * i) — one mul after the MUFUs,
            // no intermediate actB fma on the pre-shfl chain.
            const float send = role ? 0.0f : thB * actA;
            const float recv = __shfl_xor_sync(0xffffffffu, send, 16);

            float h = 0.0f;
            if (role) {
                const float actB = fmaf(bB, thB, aB);      // sigmoid(o)
                c_state = fmaf(actA, c_state, recv);       // f*c + i*g
                h = actB * tanh_fast(c_state);
                h_s[ph ^ 1][u] = h;
            }
            __syncthreads();
            if (role) g_hbuf[tt * HID + u] = h;   // post-barrier, off chain
        }
    }

    // ---- Fused FC tail: out[t,o] = W_fc[o].h_t + b_fc[o]  (2048 outputs) ----
    {
        const int o     = tid & 1;
        const int tbase = (tid >> 1) * 16;
        ulonglong2 wf[16];
        {
            const float4* wrow = reinterpret_cast<const float4*>(W_fc + o * HID);
#pragma unroll
            for (int i = 0; i < 16; ++i) {
                const float4 v = wrow[i];
                wf[i].x = pack2(v.x, v.y);
                wf[i].y = pack2(v.z, v.w);
            }
        }
        const float bias = b_fc[o];
#pragma unroll 1
        for (int k = 0; k < 16; ++k) {
            const int tt = tbase + k;
            const ulonglong2* hv =
                reinterpret_cast<const ulonglong2*>(g_hbuf + tt * HID);
            unsigned long long a0 = 0ull, a1 = 0ull, a2 = 0ull, a3 = 0ull;
#pragma unroll
            for (int i = 0; i < 16; i += 2) {
                const ulonglong2 h0 = hv[i];
                const ulonglong2 h1 = hv[i + 1];
                a0 = fma2(wf[i].x,     h0.x, a0);
                a1 = fma2(wf[i].y,     h0.y, a1);
                a2 = fma2(wf[i + 1].x, h1.x, a2);
                a3 = fma2(wf[i + 1].y, h1.y, a3);
            }
            a0 = add2(a0, a1); a2 = add2(a2, a3); a0 = add2(a0, a2);
            float lo, hi;
            asm("mov.b64 {%0, %1}, %2;" : "=f"(lo), "=f"(hi) : "l"(a0));
            out[tt * 2 + o] = (lo + hi) + bias;
        }
    }
}

extern "C" void kernel_launch(void* const* d_in, const int* in_sizes, int n_in,
                              void* d_out, int out_size)
{
    const float* x    = (const float*)d_in[0];
    const float* W_ih = (const float*)d_in[1];
    const float* W_hh = (const float*)d_in[2];
    const float* b_ih = (const float*)d_in[3];
    const float* b_hh = (const float*)d_in[4];
    const float* W_fc = (const float*)d_in[5];
    const float* b_fc = (const float*)d_in[6];
    float* out = (float*)d_out;

    lstm_seq_kernel<<<1, 128>>>(x, W_ih, W_hh, b_ih, b_hh, W_fc, b_fc, out);
}